// round 11
// baseline (speedup 1.0000x reference)
#include <cuda_runtime.h>
#include <cuda_bf16.h>
#include <cstdint>

// ---------------------------------------------------------------------------
// Problem constants
// ---------------------------------------------------------------------------
constexpr int E  = 8;
constexpr int Bb = 16384;
constexpr int Nn = 64;
constexpr int H  = 512;
constexpr int AD = 512;            // A*D

// ---------------------------------------------------------------------------
// Scratch layout (4-byte words)
// ---------------------------------------------------------------------------
constexpr long long OFF_SUMS  = 0;                          // 16384
constexpr long long OFF_MU    = OFF_SUMS  + 16384;          // 512
constexpr long long OFF_RSTD  = OFF_MU    + 512;            // 512
constexpr long long OFF_BP    = OFF_RSTD  + 512;            // 4096
constexpr long long OFF_KVB   = OFF_BP    + 4096;           // 1024
constexpr long long OFF_BOUT  = OFF_KVB   + 1024;           // 128
// weight planes
constexpr long long OFF_EHI   = OFF_BOUT  + 128;            // E*512*32 = 131072
constexpr long long OFF_ELO   = OFF_EHI   + 131072;
constexpr long long OFF_KVHI  = OFF_ELO   + 131072;         // 1024*256 = 262144
constexpr long long OFF_KVLO  = OFF_KVHI  + 262144;
constexpr long long OFF_SELHI = OFF_KVLO  + 262144;         // 512*256
constexpr long long OFF_SELLO = OFF_SELHI + 131072;
constexpr long long OFF_PREHI = OFF_SELLO + 131072;
constexpr long long OFF_PRELO = OFF_PREHI + 131072;
constexpr long long OFF_ACTHI = OFF_PRELO + 131072;
constexpr long long OFF_ACTLO = OFF_ACTHI + 131072;
constexpr long long OFF_OHI   = OFF_ACTLO + 131072;         // 128*256
constexpr long long OFF_OLO   = OFF_OHI   + 32768;
// activation planes / buffers
constexpr long long OFF_ENCH  = OFF_OLO   + 32768;          // E*B*256
constexpr long long OFF_ENCL  = OFF_ENCH  + 33554432LL;
constexpr long long OFF_KV    = OFF_ENCL  + 33554432LL;     // E*B*1024 fp32
constexpr long long OFF_PREH  = OFF_KV    + 134217728LL;    // B*256
constexpr long long OFF_PREL  = OFF_PREH  + 4194304LL;
constexpr long long OFF_SEL   = OFF_PREL  + 4194304LL;      // B*512 fp32
constexpr long long OFF_AINH  = OFF_SEL   + 8388608LL;      // B*256
constexpr long long OFF_AINL  = OFF_AINH  + 4194304LL;
constexpr long long OFF_XH    = OFF_AINL  + 4194304LL;      // B*256
constexpr long long OFF_XL    = OFF_XH    + 4194304LL;
constexpr long long SCRATCH_TOTAL = OFF_XL + 4194304LL;     // ~944 MB

__device__ __align__(256) float g_scratch[SCRATCH_TOTAL];

// ---------------------------------------------------------------------------
// Helpers
// ---------------------------------------------------------------------------
__device__ __forceinline__ uint32_t pack_split(float x, float y, uint32_t& lo)
{
    __nv_bfloat16 hx = __float2bfloat16_rn(x);
    __nv_bfloat16 hy = __float2bfloat16_rn(y);
    float rx = x - __bfloat162float(hx);
    float ry = y - __bfloat162float(hy);
    __nv_bfloat16 lx = __float2bfloat16_rn(rx);
    __nv_bfloat16 ly = __float2bfloat16_rn(ry);
    lo = (uint32_t)__bfloat16_as_ushort(lx) | ((uint32_t)__bfloat16_as_ushort(ly) << 16);
    return (uint32_t)__bfloat16_as_ushort(hx) | ((uint32_t)__bfloat16_as_ushort(hy) << 16);
}

#define MMA_BF16(d, a, b0v, b1v)                                              \
    asm volatile("mma.sync.aligned.m16n8k16.row.col.f32.bf16.bf16.f32 "       \
                 "{%0,%1,%2,%3}, {%4,%5,%6,%7}, {%8,%9}, {%0,%1,%2,%3};"      \
                 : "+f"(d[0]), "+f"(d[1]), "+f"(d[2]), "+f"(d[3])             \
                 : "r"(a[0]), "r"(a[1]), "r"(a[2]), "r"(a[3]),                \
                   "r"(b0v), "r"(b1v))

#define LDSM_X4(r, addr)                                                      \
    asm volatile("ldmatrix.sync.aligned.m8n8.x4.shared.b16 {%0,%1,%2,%3}, [%4];" \
                 : "=r"(r[0]), "=r"(r[1]), "=r"(r[2]), "=r"(r[3]) : "r"(addr))

#define CP_ASYNC16(dst, src)                                                  \
    asm volatile("cp.async.cg.shared.global [%0], [%1], 16;"                  \
                 :: "r"(dst), "l"(src) : "memory")
#define CP_COMMIT() asm volatile("cp.async.commit_group;" ::: "memory")
#define CP_WAIT(n)  asm volatile("cp.async.wait_group %0;" :: "n"(n) : "memory")

// ---------------------------------------------------------------------------
// BatchNorm stats
// ---------------------------------------------------------------------------
__global__ void bn_partial_kernel(const float* __restrict__ states, float* __restrict__ partial)
{
    int c = blockIdx.x, e = blockIdx.y, t = threadIdx.x;
    int n = t & 63, r0 = t >> 6;
    const float* sp = states + (long long)e * Bb * Nn;
    long long b = (long long)c * 1024 + r0;
    float s1 = 0.f, s2 = 0.f;
    #pragma unroll 4
    for (int it = 0; it < 256; ++it) {
        float v = sp[(b + (long long)it * 4) * Nn + n];
        s1 += v; s2 += v * v;
    }
    __shared__ float sh1[256], sh2[256];
    sh1[t] = s1; sh2[t] = s2;
    __syncthreads();
    if (t < 64) {
        float a1 = sh1[t] + sh1[t + 64] + sh1[t + 128] + sh1[t + 192];
        float a2 = sh2[t] + sh2[t + 64] + sh2[t + 128] + sh2[t + 192];
        long long base = ((long long)e * 16 + c) * 64 + t;
        partial[base] = a1;
        partial[8192 + base] = a2;
    }
}

__global__ void bn_final_kernel(const float* __restrict__ partial,
                                float* __restrict__ mu, float* __restrict__ rstd)
{
    int idx = blockIdx.x * blockDim.x + threadIdx.x;
    if (idx >= E * Nn) return;
    int e = idx >> 6, n = idx & 63;
    float s1 = 0.f, s2 = 0.f;
    for (int c = 0; c < 16; ++c) {
        long long base = ((long long)e * 16 + c) * 64 + n;
        s1 += partial[base];
        s2 += partial[8192 + base];
    }
    float m = s1 * (1.f / Bb);
    float var = s2 * (1.f / Bb) - m * m;
    mu[idx] = m;
    rstd[idx] = rsqrtf(var + 1e-5f);
}

// ---------------------------------------------------------------------------
// Merged encoder fold: BN-folded weight split + bias, one launch
// ---------------------------------------------------------------------------
__global__ void enc_fold_kernel(const float* __restrict__ W_enc, const float* __restrict__ b_enc,
                                const float* __restrict__ mu, const float* __restrict__ rstd,
                                uint32_t* __restrict__ hi, uint32_t* __restrict__ lo,
                                float* __restrict__ bp)
{
    int idx = blockIdx.x * blockDim.x + threadIdx.x;   // E*H*32
    if (idx >= E * H * 32) return;
    int h = idx & 511;
    int rest = idx >> 9;
    int p = rest & 31;
    int e = rest >> 5;
    int k = 2 * p;
    float w0 = rstd[e * 64 + k]     * W_enc[((long long)e * 64 + k) * H + h];
    float w1 = rstd[e * 64 + k + 1] * W_enc[((long long)e * 64 + k + 1) * H + h];
    uint32_t l; uint32_t hh = pack_split(w0, w1, l);
    long long o = ((long long)e * 512 + h) * 32 + p;
    hi[o] = hh; lo[o] = l;
    if (p == 0) {
        float bacc = b_enc[e * H + h];
        #pragma unroll 8
        for (int n = 0; n < Nn; ++n)
            bacc -= mu[e * 64 + n] * rstd[e * 64 + n] * W_enc[((long long)e * 64 + n) * H + h];
        bp[e * H + h] = bacc;
    }
}

// ---------------------------------------------------------------------------
// Other weight-prep kernels
// ---------------------------------------------------------------------------
__global__ void kv_pack_kernel(const float* __restrict__ Wk, const float* __restrict__ Wv,
                               const float* __restrict__ bv,
                               uint32_t* __restrict__ hi, uint32_t* __restrict__ lo,
                               float* __restrict__ kvbias)
{
    int idx = blockIdx.x * blockDim.x + threadIdx.x;   // 1024*256
    if (idx >= 1024 * 256) return;
    int p = idx & 255, n = idx >> 8;
    bool isv = n >= 512;
    int a = (n & 511) >> 6, dd = n & 63;
    const float* W = isv ? Wv : Wk;
    int k = 2 * p;
    float w0 = W[((long long)a * H + k) * 64 + dd];
    float w1 = W[((long long)a * H + k + 1) * 64 + dd];
    uint32_t l; uint32_t hh = pack_split(w0, w1, l);
    hi[idx] = hh; lo[idx] = l;
    if (p == 0) kvbias[n] = isv ? bv[n - 512] : 0.f;
}

__global__ void sel_pack_kernel(const float* __restrict__ Wsel,
                                uint32_t* __restrict__ hi, uint32_t* __restrict__ lo)
{
    int idx = blockIdx.x * blockDim.x + threadIdx.x;   // 512*256
    if (idx >= 512 * 256) return;
    int p = idx & 255, n = idx >> 8;
    int a = n >> 6, dd = n & 63;
    int k = 2 * p;
    float w0 = Wsel[((long long)a * H + k) * 64 + dd];
    float w1 = Wsel[((long long)a * H + k + 1) * 64 + dd];
    uint32_t l; uint32_t hh = pack_split(w0, w1, l);
    hi[idx] = hh; lo[idx] = l;
}

__global__ void mat_split_kernel(const float* __restrict__ W,   // [512][512] k x n
                                 uint32_t* __restrict__ hi, uint32_t* __restrict__ lo)
{
    int idx = blockIdx.x * blockDim.x + threadIdx.x;   // 512*256
    if (idx >= 512 * 256) return;
    int p = idx & 255, n = idx >> 8;
    float w0 = W[(long long)(2 * p) * 512 + n];
    float w1 = W[(long long)(2 * p + 1) * 512 + n];
    uint32_t l; uint32_t hh = pack_split(w0, w1, l);
    hi[idx] = hh; lo[idx] = l;
}

__global__ void out_pack_kernel(const float* __restrict__ W_mean, const float* __restrict__ W_logstd,
                                const float* __restrict__ b_mean, const float* __restrict__ b_logstd,
                                uint32_t* __restrict__ hi, uint32_t* __restrict__ lo,
                                float* __restrict__ bout)
{
    int idx = blockIdx.x * blockDim.x + threadIdx.x;   // 128*256
    if (idx >= 128 * 256) return;
    int p = idx & 255, n = idx >> 8;
    const float* W = (n < 64) ? W_mean : W_logstd;
    int j = n & 63;
    float w0 = W[(long long)(2 * p) * 64 + j];
    float w1 = W[(long long)(2 * p + 1) * 64 + j];
    uint32_t l; uint32_t hh = pack_split(w0, w1, l);
    hi[idx] = hh; lo[idx] = l;
    if (p == 0) bout[n] = (n < 64) ? b_mean[j] : b_logstd[j];
}

// ---------------------------------------------------------------------------
// Split-bf16 tensor-core GEMM, CTA tile 128 x TN, 8 warps x (64 x TN/4).
//   ASRC: 0 = A fp32 (split on the fly, 2-stage register pipeline)
//         1 = A pre-split hi/lo planes [M][K/2] (4-stage cp.async pipeline)
//   ACT : 0 none, 1 leaky, 2 relu, 3 kv-mode (leaky iff col>=512), 4 out-split+clip
//   OUTM: 0 = fp32 C [M][N], 1 = hi/lo planes [M][N/2]
// ---------------------------------------------------------------------------
template <int ACT, int OUTM, int ASRC, int TN>
__global__ __launch_bounds__(256, 1)
void mma_gemm_kernel(const float* __restrict__ Af,
                     const uint32_t* __restrict__ AhiG, const uint32_t* __restrict__ AloG,
                     const uint32_t* __restrict__ BhiG, const uint32_t* __restrict__ BloG,
                     const float* __restrict__ biasg,
                     float* __restrict__ Cf,
                     uint32_t* __restrict__ ChiG, uint32_t* __restrict__ CloG,
                     int M, int N, int K,
                     long long sA, long long sBw, long long sBias, long long sC)
{
    constexpr int ASZ = 128 * 12;          // words per A plane
    constexpr int BSZ = TN * 12;           // words per B plane
    constexpr int BUFW = 2 * ASZ + 2 * BSZ;
    constexpr int WNT = TN / 4;            // warp n-tile
    constexpr int NJ = WNT / 8;            // n8 tiles per warp
    constexpr int NB = WNT / 16;           // LDSM.x4 per B plane per warp
    constexpr int RB = TN / 128;           // B rows staged per thread
    constexpr int S = (ASRC == 1) ? 4 : 2; // pipeline stages

    extern __shared__ uint32_t sm[];

    const int bz = blockIdx.z;
    const float* Ab = (ASRC == 0) ? (Af + bz * sA) : nullptr;
    const uint32_t* AhB = (ASRC == 1) ? (AhiG + bz * sA) : nullptr;
    const uint32_t* AlB = (ASRC == 1) ? (AloG + bz * sA) : nullptr;
    const uint32_t* BhB = BhiG + bz * sBw;
    const uint32_t* BlB = BloG + bz * sBw;
    const float* bias = biasg ? (biasg + bz * sBias) : nullptr;
    float* C = Cf ? (Cf + bz * sC) : nullptr;
    uint32_t* Chi = ChiG ? (ChiG + bz * sC) : nullptr;
    uint32_t* Clo = CloG ? (CloG + bz * sC) : nullptr;

    const int t = threadIdx.x;
    const int lane = t & 31;
    const int warp = t >> 5;
    const int wm = warp >> 2;           // 0..1
    const int wn = warp & 3;            // 0..3
    const int m0 = blockIdx.y * 128;
    const int n0 = blockIdx.x * TN;
    const int Kw = K >> 1;

    // staging roles
    const int am = t >> 1;              // A row 0..127
    const int ak = t & 1;               // A k-half
    const int bpl = t >> 7;             // B plane 0=hi 1=lo
    const int bn0 = (t & 127) * RB;     // B first row

    float acc[4][NJ][4];
    #pragma unroll
    for (int i = 0; i < 4; ++i)
        #pragma unroll
        for (int j = 0; j < NJ; ++j)
            #pragma unroll
            for (int q = 0; q < 4; ++q) acc[i][j][q] = 0.f;

    const uint32_t sbase = (uint32_t)__cvta_generic_to_shared(sm);
    const uint32_t BUFB = BUFW * 4;     // bytes per buffer
    const uint32_t aoff = (((uint32_t)(wm * 64 + (lane & 15)) * 12 + (lane >> 4) * 4)) * 4;
    const uint32_t boff = (((uint32_t)(wn * WNT + (lane & 7) + ((lane >> 4) & 1) * 8) * 12
                            + ((lane >> 3) & 1) * 4)) * 4;

    const int NC = K >> 4;              // chunks of 16

    auto mma_step = [&](int buf) {
        const uint32_t b0 = sbase + (uint32_t)buf * BUFB;
        uint32_t AH[4][4], AL[4][4], BH[NB][4], BL[NB][4];
        #pragma unroll
        for (int i = 0; i < 4; ++i) {
            LDSM_X4(AH[i], b0 + aoff + i * (16 * 12 * 4));
            LDSM_X4(AL[i], b0 + ASZ * 4 + aoff + i * (16 * 12 * 4));
        }
        #pragma unroll
        for (int j = 0; j < NB; ++j) {
            LDSM_X4(BH[j], b0 + 2 * ASZ * 4 + boff + j * (16 * 12 * 4));
            LDSM_X4(BL[j], b0 + 2 * ASZ * 4 + BSZ * 4 + boff + j * (16 * 12 * 4));
        }
        #pragma unroll
        for (int i = 0; i < 4; ++i)
            #pragma unroll
            for (int jj = 0; jj < NJ; ++jj) {
                const int jm = jj >> 1, js = (jj & 1) * 2;
                MMA_BF16(acc[i][jj], AH[i], BH[jm][js], BH[jm][js + 1]);
                MMA_BF16(acc[i][jj], AH[i], BL[jm][js], BL[jm][js + 1]);
                MMA_BF16(acc[i][jj], AL[i], BH[jm][js], BH[jm][js + 1]);
            }
    };

    if constexpr (ASRC == 1) {
        // ---- 4-stage cp.async pipeline (pure-copy staging) ----
        const uint32_t aDh = sbase + (uint32_t)(am * 12 + ak * 4) * 4;
        const uint32_t aDl = aDh + ASZ * 4;
        const uint32_t bD  = sbase + (uint32_t)(2 * ASZ + bpl * BSZ + bn0 * 12) * 4;
        const uint32_t* ahp = AhB + (long long)(m0 + am) * Kw + ak * 4;
        const uint32_t* alp = AlB + (long long)(m0 + am) * Kw + ak * 4;
        const uint32_t* bpg = (bpl ? BlB : BhB) + (long long)(n0 + bn0) * Kw;

        auto issue = [&](int c) {
            if (c < NC) {
                const uint32_t bo = (uint32_t)(c % S) * BUFB;
                const int kw = c * 8;
                CP_ASYNC16(aDh + bo, ahp + kw);
                CP_ASYNC16(aDl + bo, alp + kw);
                #pragma unroll
                for (int r = 0; r < RB; ++r) {
                    const uint32_t* src = bpg + (long long)r * Kw + kw;
                    CP_ASYNC16(bD + bo + r * 48, src);
                    CP_ASYNC16(bD + bo + r * 48 + 16, src + 4);
                }
            }
            CP_COMMIT();
        };

        #pragma unroll
        for (int p = 0; p < S - 1; ++p) issue(p);

        #pragma unroll 1
        for (int c = 0; c < NC; ++c) {
            CP_WAIT(S - 2);          // chunk c resident (in-order group completion)
            __syncthreads();
            issue(c + S - 1);        // refill the buffer consumed at iter c-1
            mma_step(c % S);
        }
    } else {
        // ---- 2-stage register pipeline with on-the-fly fp32->hi/lo split ----
        const float* aptrf = Ab + (long long)(m0 + am) * K + ak * 8;
        const uint32_t* bptr = (bpl ? BlB : BhB) + (long long)(n0 + bn0) * Kw;
        uint32_t* aS_h = sm + am * 12 + ak * 4;
        uint32_t* aS_l = aS_h + ASZ;
        uint32_t* bS = sm + 2 * ASZ + bpl * BSZ + bn0 * 12;

        float4 av0, av1;
        uint4 bv[RB][2];

        auto load_chunk = [&](int k0) {
            av0 = *(const float4*)(aptrf + k0);
            av1 = *(const float4*)(aptrf + k0 + 4);
            #pragma unroll
            for (int r = 0; r < RB; ++r) {
                bv[r][0] = *(const uint4*)(bptr + (long long)r * Kw + (k0 >> 1));
                bv[r][1] = *(const uint4*)(bptr + (long long)r * Kw + (k0 >> 1) + 4);
            }
        };
        auto store_smem = [&](int buf) {
            float v[8] = {av0.x, av0.y, av0.z, av0.w, av1.x, av1.y, av1.z, av1.w};
            uint32_t hi[4], lo[4];
            #pragma unroll
            for (int j = 0; j < 4; ++j) hi[j] = pack_split(v[2 * j], v[2 * j + 1], lo[j]);
            *(uint4*)(aS_h + buf * BUFW) = make_uint4(hi[0], hi[1], hi[2], hi[3]);
            *(uint4*)(aS_l + buf * BUFW) = make_uint4(lo[0], lo[1], lo[2], lo[3]);
            #pragma unroll
            for (int r = 0; r < RB; ++r) {
                *(uint4*)(bS + buf * BUFW + r * 12) = bv[r][0];
                *(uint4*)(bS + buf * BUFW + r * 12 + 4) = bv[r][1];
            }
        };

        load_chunk(0);
        store_smem(0);
        __syncthreads();
        int buf = 0;
        for (int k0 = 16; k0 < K; k0 += 16) {
            load_chunk(k0);
            mma_step(buf);
            store_smem(buf ^ 1);
            __syncthreads();
            buf ^= 1;
        }
        mma_step(buf);
    }

    // ---- epilogue ----
    const int g = lane >> 2, tq = lane & 3;
    const int Nw = N >> 1;
    #pragma unroll
    for (int i = 0; i < 4; ++i) {
        const int row = m0 + wm * 64 + i * 16 + g;
        #pragma unroll
        for (int jj = 0; jj < NJ; ++jj) {
            const int col = n0 + wn * WNT + jj * 8 + tq * 2;
            float b0v = bias ? bias[col] : 0.f;
            float b1v = bias ? bias[col + 1] : 0.f;
            float v00 = acc[i][jj][0] + b0v, v01 = acc[i][jj][1] + b1v;
            float v10 = acc[i][jj][2] + b0v, v11 = acc[i][jj][3] + b1v;
            if (ACT == 1) {
                v00 = v00 >= 0.f ? v00 : 0.01f * v00;
                v01 = v01 >= 0.f ? v01 : 0.01f * v01;
                v10 = v10 >= 0.f ? v10 : 0.01f * v10;
                v11 = v11 >= 0.f ? v11 : 0.01f * v11;
            } else if (ACT == 2) {
                v00 = fmaxf(v00, 0.f); v01 = fmaxf(v01, 0.f);
                v10 = fmaxf(v10, 0.f); v11 = fmaxf(v11, 0.f);
            } else if (ACT == 3) {
                if (col >= 512) {
                    v00 = v00 >= 0.f ? v00 : 0.01f * v00;
                    v01 = v01 >= 0.f ? v01 : 0.01f * v01;
                    v10 = v10 >= 0.f ? v10 : 0.01f * v10;
                    v11 = v11 >= 0.f ? v11 : 0.01f * v11;
                }
            }
            if (ACT == 4) {
                const long long base2 = (long long)M * 64;
                float vv[4] = {v00, v01, v10, v11};
                int rr[4] = {row, row, row + 8, row + 8};
                int cc[4] = {col, col + 1, col, col + 1};
                #pragma unroll
                for (int q = 0; q < 4; ++q) {
                    if (cc[q] < 64) {
                        C[(long long)rr[q] * 64 + cc[q]] = vv[q];
                    } else {
                        float x = fminf(fmaxf(vv[q], -20.f), 2.f);
                        C[base2 + (long long)rr[q] * 64 + (cc[q] - 64)] = x;
                    }
                }
            } else if (OUTM == 1) {
                uint32_t l0, l1;
                uint32_t h0 = pack_split(v00, v01, l0);
                uint32_t h1 = pack_split(v10, v11, l1);
                Chi[(long long)row * Nw + (col >> 1)] = h0;
                Clo[(long long)row * Nw + (col >> 1)] = l0;
                Chi[(long long)(row + 8) * Nw + (col >> 1)] = h1;
                Clo[(long long)(row + 8) * Nw + (col >> 1)] = l1;
            } else {
                *(float2*)&C[(long long)row * N + col] = make_float2(v00, v01);
                *(float2*)&C[(long long)(row + 8) * N + col] = make_float2(v10, v11);
            }
        }
    }
}

// ---------------------------------------------------------------------------
// Attention over KV [e][b][1024] (keys 0..511, vals 512..1023); sel fp32.
// ---------------------------------------------------------------------------
__global__ void attn_kernel(const float* __restrict__ KV, const float* __restrict__ sel,
                            float* __restrict__ actor_in,
                            uint32_t* __restrict__ ain_hi, uint32_t* __restrict__ ain_lo)
{
    const int b = blockIdx.x;
    const int a = threadIdx.x >> 5;
    const int lane = threadIdx.x & 31;
    const int colbase = a * 64 + lane * 2;

    const float2 s2 = *reinterpret_cast<const float2*>(&sel[(long long)b * AD + colbase]);

    float v0[E], v1[E], logit[E];
    #pragma unroll
    for (int e = 0; e < E; ++e) {
        long long off = ((long long)e * Bb + b) * 1024 + colbase;
        float2 k2 = *reinterpret_cast<const float2*>(&KV[off]);
        float2 vv = *reinterpret_cast<const float2*>(&KV[off + 512]);
        v0[e] = vv.x; v1[e] = vv.y;
        float p = s2.x * k2.x + s2.y * k2.y;
        #pragma unroll
        for (int o = 16; o >= 1; o >>= 1) p += __shfl_xor_sync(0xffffffffu, p, o);
        logit[e] = p * 0.125f;
    }
    float mx = logit[0];
    #pragma unroll
    for (int e = 1; e < E; ++e) mx = fmaxf(mx, logit[e]);
    float den = 0.f, w[E];
    #pragma unroll
    for (int e = 0; e < E; ++e) { w[e] = __expf(logit[e] - mx); den += w[e]; }
    float inv = 1.f / den;
    float a0 = 0.f, a1 = 0.f;
    #pragma unroll
    for (int e = 0; e < E; ++e) {
        float we = w[e] * inv;
        a0 += we * v0[e];
        a1 += we * v1[e];
    }
    *reinterpret_cast<float2*>(&actor_in[(long long)b * AD + colbase]) = make_float2(a0, a1);
    uint32_t l; uint32_t h = pack_split(a0, a1, l);
    long long po = (long long)b * 256 + (colbase >> 1);
    ain_hi[po] = h;
    ain_lo[po] = l;
}

// ---------------------------------------------------------------------------
// Launch
// ---------------------------------------------------------------------------
constexpr int BUFB_256 = (2 * 128 * 12 + 2 * 256 * 12) * 4;   // 36864 B
constexpr int BUFB_128 = (2 * 128 * 12 + 2 * 128 * 12) * 4;   // 24576 B
constexpr int SM_A0_256 = 2 * BUFB_256;   // 73728  (ASRC=0, 2-stage)
constexpr int SM_A1_256 = 4 * BUFB_256;   // 147456 (ASRC=1, 4-stage)
constexpr int SM_A1_128 = 4 * BUFB_128;   // 98304

extern "C" void kernel_launch(void* const* d_in, const int* in_sizes, int n_in,
                              void* d_out, int out_size)
{
    float* S = nullptr;
    cudaGetSymbolAddress((void**)&S, g_scratch);
    uint32_t* Su = (uint32_t*)S;

    const float* states      = (const float*)d_in[0];
    const float* pre_actions = (const float*)d_in[1];
    const float* W_enc       = (const float*)d_in[2];
    const float* b_enc       = (const float*)d_in[3];
    const float* W_pre       = (const float*)d_in[4];
    const float* b_pre       = (const float*)d_in[5];
    const float* Wk          = (const float*)d_in[6];
    const float* Wsel        = (const float*)d_in[7];
    const float* Wv          = (const float*)d_in[8];
    const float* bv          = (const float*)d_in[9];
    const float* W_actor     = (const float*)d_in[10];
    const float* b_actor     = (const float*)d_in[11];
    const float* W_mean      = (const float*)d_in[12];
    const float* b_mean      = (const float*)d_in[13];
    const float* W_logstd    = (const float*)d_in[14];
    const float* b_logstd    = (const float*)d_in[15];

    float* out = (float*)d_out;
    float* actor_in = out + 2LL * Bb * 64;   // third output region

    cudaFuncSetAttribute(mma_gemm_kernel<1, 1, 0, 256>, cudaFuncAttributeMaxDynamicSharedMemorySize, SM_A0_256);
    cudaFuncSetAttribute(mma_gemm_kernel<3, 0, 1, 256>, cudaFuncAttributeMaxDynamicSharedMemorySize, SM_A1_256);
    cudaFuncSetAttribute(mma_gemm_kernel<0, 0, 1, 256>, cudaFuncAttributeMaxDynamicSharedMemorySize, SM_A1_256);
    cudaFuncSetAttribute(mma_gemm_kernel<2, 1, 1, 256>, cudaFuncAttributeMaxDynamicSharedMemorySize, SM_A1_256);
    cudaFuncSetAttribute(mma_gemm_kernel<4, 0, 1, 128>, cudaFuncAttributeMaxDynamicSharedMemorySize, SM_A1_128);

    // Launch order puts the big KV GEMM at index 5 for the ncu -s 5 -c 1 capture.
    bn_partial_kernel<<<dim3(16, E), 256>>>(states, S + OFF_SUMS);                       // 0
    bn_final_kernel<<<2, 256>>>(S + OFF_SUMS, S + OFF_MU, S + OFF_RSTD);                 // 1
    enc_fold_kernel<<<512, 256>>>(W_enc, b_enc, S + OFF_MU, S + OFF_RSTD,
                                  Su + OFF_EHI, Su + OFF_ELO, S + OFF_BP);               // 2
    kv_pack_kernel<<<1024, 256>>>(Wk, Wv, bv, Su + OFF_KVHI, Su + OFF_KVLO, S + OFF_KVB);// 3

    // 4: encoder — enc planes = leaky(states @ Wenc' + bp)
    mma_gemm_kernel<1, 1, 0, 256><<<dim3(2, 128, E), 256, SM_A0_256>>>(
        states, nullptr, nullptr, Su + OFF_EHI, Su + OFF_ELO, S + OFF_BP,
        nullptr, Su + OFF_ENCH, Su + OFF_ENCL,
        Bb, H, Nn,
        (long long)Bb * Nn, 512LL * 32, 512LL, (long long)Bb * 256);

    // 5: fused keys|vals — KV = encs @ [Wk|Wv] (+bv, leaky on vals)
    mma_gemm_kernel<3, 0, 1, 256><<<dim3(4, 128, E), 256, SM_A1_256>>>(
        nullptr, Su + OFF_ENCH, Su + OFF_ENCL, Su + OFF_KVHI, Su + OFF_KVLO, S + OFF_KVB,
        S + OFF_KV, nullptr, nullptr,
        Bb, 1024, H,
        (long long)Bb * 256, 0LL, 0LL, (long long)Bb * 1024);

    sel_pack_kernel<<<512, 256>>>(Wsel, Su + OFF_SELHI, Su + OFF_SELLO);                 // 6
    mat_split_kernel<<<512, 256>>>(W_pre, Su + OFF_PREHI, Su + OFF_PRELO);               // 7
    mat_split_kernel<<<512, 256>>>(W_actor, Su + OFF_ACTHI, Su + OFF_ACTLO);             // 8
    out_pack_kernel<<<128, 256>>>(W_mean, W_logstd, b_mean, b_logstd,
                                  Su + OFF_OHI, Su + OFF_OLO, S + OFF_BOUT);             // 9

    // 10: pre planes = leaky(pre_actions @ W_pre + b_pre)
    mma_gemm_kernel<1, 1, 0, 256><<<dim3(2, 128, 1), 256, SM_A0_256>>>(
        pre_actions, nullptr, nullptr, Su + OFF_PREHI, Su + OFF_PRELO, b_pre,
        nullptr, Su + OFF_PREH, Su + OFF_PREL,
        Bb, H, H, 0LL, 0LL, 0LL, 0LL);

    // 11: sel = pre @ Wsel
    mma_gemm_kernel<0, 0, 1, 256><<<dim3(2, 128, 1), 256, SM_A1_256>>>(
        nullptr, Su + OFF_PREH, Su + OFF_PREL, Su + OFF_SELHI, Su + OFF_SELLO, nullptr,
        S + OFF_SEL, nullptr, nullptr,
        Bb, AD, H, 0LL, 0LL, 0LL, 0LL);

    // 12: attention -> actor_in fp32 (d_out) + planes
    attn_kernel<<<Bb, 256>>>(S + OFF_KV, S + OFF_SEL, actor_in,
                             Su + OFF_AINH, Su + OFF_AINL);

    // 13: x planes = relu(actor_in @ W_actor + b_actor)
    mma_gemm_kernel<2, 1, 1, 256><<<dim3(2, 128, 1), 256, SM_A1_256>>>(
        nullptr, Su + OFF_AINH, Su + OFF_AINL, Su + OFF_ACTHI, Su + OFF_ACTLO, b_actor,
        nullptr, Su + OFF_XH, Su + OFF_XL,
        Bb, H, H, 0LL, 0LL, 0LL, 0LL);

    // 14: fused output GEMM — [mean | clip(logstd)] -> d_out
    mma_gemm_kernel<4, 0, 1, 128><<<dim3(1, 128, 1), 256, SM_A1_128>>>(
        nullptr, Su + OFF_XH, Su + OFF_XL, Su + OFF_OHI, Su + OFF_OLO, S + OFF_BOUT,
        out, nullptr, nullptr,
        Bb, 128, H, 0LL, 0LL, 0LL, 0LL);
}

// round 12
// speedup vs baseline: 1.2122x; 1.2122x over previous
#include <cuda_runtime.h>
#include <cuda_bf16.h>
#include <cuda_fp16.h>
#include <cstdint>

// ---------------------------------------------------------------------------
// Problem constants
// ---------------------------------------------------------------------------
constexpr int E  = 8;
constexpr int Bb = 16384;
constexpr int Nn = 64;
constexpr int H  = 512;
constexpr int AD = 512;            // A*D

// ---------------------------------------------------------------------------
// Scratch layout (4-byte words)
// ---------------------------------------------------------------------------
constexpr long long OFF_SUMS  = 0;                          // 16384
constexpr long long OFF_MU    = OFF_SUMS  + 16384;          // 512
constexpr long long OFF_RSTD  = OFF_MU    + 512;            // 512
constexpr long long OFF_BP    = OFF_RSTD  + 512;            // 4096
constexpr long long OFF_KVB   = OFF_BP    + 4096;           // 1024
constexpr long long OFF_BOUT  = OFF_KVB   + 1024;           // 128
// weight planes
constexpr long long OFF_EHI   = OFF_BOUT  + 128;            // E*512*32 = 131072
constexpr long long OFF_ELO   = OFF_EHI   + 131072;
constexpr long long OFF_KVHI  = OFF_ELO   + 131072;         // 1024*256 (single fp16 plane)
constexpr long long OFF_KVLO  = OFF_KVHI  + 262144;         // (unused)
constexpr long long OFF_SELHI = OFF_KVLO  + 262144;         // 512*256
constexpr long long OFF_SELLO = OFF_SELHI + 131072;
constexpr long long OFF_PREHI = OFF_SELLO + 131072;
constexpr long long OFF_PRELO = OFF_PREHI + 131072;
constexpr long long OFF_ACTHI = OFF_PRELO + 131072;
constexpr long long OFF_ACTLO = OFF_ACTHI + 131072;
constexpr long long OFF_OHI   = OFF_ACTLO + 131072;         // 128*256
constexpr long long OFF_OLO   = OFF_OHI   + 32768;
// activation planes / buffers
constexpr long long OFF_ENCH  = OFF_OLO   + 32768;          // E*B*256 (fp16 hi)
constexpr long long OFF_ENCL  = OFF_ENCH  + 33554432LL;     // (fp16 lo)
constexpr long long OFF_KV    = OFF_ENCL  + 33554432LL;     // E*B*1024 fp32
constexpr long long OFF_PREH  = OFF_KV    + 134217728LL;    // B*256
constexpr long long OFF_PREL  = OFF_PREH  + 4194304LL;
constexpr long long OFF_SEL   = OFF_PREL  + 4194304LL;      // B*512 fp32
constexpr long long OFF_AINH  = OFF_SEL   + 8388608LL;      // B*256
constexpr long long OFF_AINL  = OFF_AINH  + 4194304LL;
constexpr long long OFF_XH    = OFF_AINL  + 4194304LL;      // B*256
constexpr long long OFF_XL    = OFF_XH    + 4194304LL;
constexpr long long SCRATCH_TOTAL = OFF_XL + 4194304LL;     // ~944 MB

__device__ __align__(256) float g_scratch[SCRATCH_TOTAL];

// ---------------------------------------------------------------------------
// Helpers
// ---------------------------------------------------------------------------
__device__ __forceinline__ uint32_t pack_split(float x, float y, uint32_t& lo)
{
    __nv_bfloat16 hx = __float2bfloat16_rn(x);
    __nv_bfloat16 hy = __float2bfloat16_rn(y);
    float rx = x - __bfloat162float(hx);
    float ry = y - __bfloat162float(hy);
    __nv_bfloat16 lx = __float2bfloat16_rn(rx);
    __nv_bfloat16 ly = __float2bfloat16_rn(ry);
    lo = (uint32_t)__bfloat16_as_ushort(lx) | ((uint32_t)__bfloat16_as_ushort(ly) << 16);
    return (uint32_t)__bfloat16_as_ushort(hx) | ((uint32_t)__bfloat16_as_ushort(hy) << 16);
}

__device__ __forceinline__ uint32_t pack_split_f16(float x, float y, uint32_t& lo)
{
    __half hx = __float2half_rn(x);
    __half hy = __float2half_rn(y);
    float rx = x - __half2float(hx);
    float ry = y - __half2float(hy);
    __half lx = __float2half_rn(rx);
    __half ly = __float2half_rn(ry);
    lo = (uint32_t)__half_as_ushort(lx) | ((uint32_t)__half_as_ushort(ly) << 16);
    return (uint32_t)__half_as_ushort(hx) | ((uint32_t)__half_as_ushort(hy) << 16);
}

__device__ __forceinline__ uint32_t pack_f16(float x, float y)
{
    __half hx = __float2half_rn(x);
    __half hy = __float2half_rn(y);
    return (uint32_t)__half_as_ushort(hx) | ((uint32_t)__half_as_ushort(hy) << 16);
}

#define MMA_BF16(d, a, b0v, b1v)                                              \
    asm volatile("mma.sync.aligned.m16n8k16.row.col.f32.bf16.bf16.f32 "       \
                 "{%0,%1,%2,%3}, {%4,%5,%6,%7}, {%8,%9}, {%0,%1,%2,%3};"      \
                 : "+f"(d[0]), "+f"(d[1]), "+f"(d[2]), "+f"(d[3])             \
                 : "r"(a[0]), "r"(a[1]), "r"(a[2]), "r"(a[3]),                \
                   "r"(b0v), "r"(b1v))

#define MMA_F16(d, a, b0v, b1v)                                               \
    asm volatile("mma.sync.aligned.m16n8k16.row.col.f32.f16.f16.f32 "         \
                 "{%0,%1,%2,%3}, {%4,%5,%6,%7}, {%8,%9}, {%0,%1,%2,%3};"      \
                 : "+f"(d[0]), "+f"(d[1]), "+f"(d[2]), "+f"(d[3])             \
                 : "r"(a[0]), "r"(a[1]), "r"(a[2]), "r"(a[3]),                \
                   "r"(b0v), "r"(b1v))

#define LDSM_X4(r, addr)                                                      \
    asm volatile("ldmatrix.sync.aligned.m8n8.x4.shared.b16 {%0,%1,%2,%3}, [%4];" \
                 : "=r"(r[0]), "=r"(r[1]), "=r"(r[2]), "=r"(r[3]) : "r"(addr))

// ---------------------------------------------------------------------------
// BatchNorm stats
// ---------------------------------------------------------------------------
__global__ void bn_partial_kernel(const float* __restrict__ states, float* __restrict__ partial)
{
    int c = blockIdx.x, e = blockIdx.y, t = threadIdx.x;
    int n = t & 63, r0 = t >> 6;
    const float* sp = states + (long long)e * Bb * Nn;
    long long b = (long long)c * 1024 + r0;
    float s1 = 0.f, s2 = 0.f;
    #pragma unroll 4
    for (int it = 0; it < 256; ++it) {
        float v = sp[(b + (long long)it * 4) * Nn + n];
        s1 += v; s2 += v * v;
    }
    __shared__ float sh1[256], sh2[256];
    sh1[t] = s1; sh2[t] = s2;
    __syncthreads();
    if (t < 64) {
        float a1 = sh1[t] + sh1[t + 64] + sh1[t + 128] + sh1[t + 192];
        float a2 = sh2[t] + sh2[t + 64] + sh2[t + 128] + sh2[t + 192];
        long long base = ((long long)e * 16 + c) * 64 + t;
        partial[base] = a1;
        partial[8192 + base] = a2;
    }
}

__global__ void bn_final_kernel(const float* __restrict__ partial,
                                float* __restrict__ mu, float* __restrict__ rstd)
{
    int idx = blockIdx.x * blockDim.x + threadIdx.x;
    if (idx >= E * Nn) return;
    int e = idx >> 6, n = idx & 63;
    float s1 = 0.f, s2 = 0.f;
    for (int c = 0; c < 16; ++c) {
        long long base = ((long long)e * 16 + c) * 64 + n;
        s1 += partial[base];
        s2 += partial[8192 + base];
    }
    float m = s1 * (1.f / Bb);
    float var = s2 * (1.f / Bb) - m * m;
    mu[idx] = m;
    rstd[idx] = rsqrtf(var + 1e-5f);
}

// ---------------------------------------------------------------------------
// Merged encoder fold: BN-folded weight split (bf16 planes) + bias
// ---------------------------------------------------------------------------
__global__ void enc_fold_kernel(const float* __restrict__ W_enc, const float* __restrict__ b_enc,
                                const float* __restrict__ mu, const float* __restrict__ rstd,
                                uint32_t* __restrict__ hi, uint32_t* __restrict__ lo,
                                float* __restrict__ bp)
{
    int idx = blockIdx.x * blockDim.x + threadIdx.x;   // E*H*32
    if (idx >= E * H * 32) return;
    int h = idx & 511;
    int rest = idx >> 9;
    int p = rest & 31;
    int e = rest >> 5;
    int k = 2 * p;
    float w0 = rstd[e * 64 + k]     * W_enc[((long long)e * 64 + k) * H + h];
    float w1 = rstd[e * 64 + k + 1] * W_enc[((long long)e * 64 + k + 1) * H + h];
    uint32_t l; uint32_t hh = pack_split(w0, w1, l);
    long long o = ((long long)e * 512 + h) * 32 + p;
    hi[o] = hh; lo[o] = l;
    if (p == 0) {
        float bacc = b_enc[e * H + h];
        #pragma unroll 8
        for (int n = 0; n < Nn; ++n)
            bacc -= mu[e * 64 + n] * rstd[e * 64 + n] * W_enc[((long long)e * 64 + n) * H + h];
        bp[e * H + h] = bacc;
    }
}

// ---------------------------------------------------------------------------
// KV weights: single plain-fp16 plane [1024][256 words]
// ---------------------------------------------------------------------------
__global__ void kv_pack_kernel(const float* __restrict__ Wk, const float* __restrict__ Wv,
                               const float* __restrict__ bv,
                               uint32_t* __restrict__ wplane, float* __restrict__ kvbias)
{
    int idx = blockIdx.x * blockDim.x + threadIdx.x;   // 1024*256
    if (idx >= 1024 * 256) return;
    int p = idx & 255, n = idx >> 8;
    bool isv = n >= 512;
    int a = (n & 511) >> 6, dd = n & 63;
    const float* W = isv ? Wv : Wk;
    int k = 2 * p;
    float w0 = W[((long long)a * H + k) * 64 + dd];
    float w1 = W[((long long)a * H + k + 1) * 64 + dd];
    wplane[idx] = pack_f16(w0, w1);
    if (p == 0) kvbias[n] = isv ? bv[n - 512] : 0.f;
}

__global__ void sel_pack_kernel(const float* __restrict__ Wsel,
                                uint32_t* __restrict__ hi, uint32_t* __restrict__ lo)
{
    int idx = blockIdx.x * blockDim.x + threadIdx.x;   // 512*256
    if (idx >= 512 * 256) return;
    int p = idx & 255, n = idx >> 8;
    int a = n >> 6, dd = n & 63;
    int k = 2 * p;
    float w0 = Wsel[((long long)a * H + k) * 64 + dd];
    float w1 = Wsel[((long long)a * H + k + 1) * 64 + dd];
    uint32_t l; uint32_t hh = pack_split(w0, w1, l);
    hi[idx] = hh; lo[idx] = l;
}

__global__ void mat_split_kernel(const float* __restrict__ W,   // [512][512] k x n
                                 uint32_t* __restrict__ hi, uint32_t* __restrict__ lo)
{
    int idx = blockIdx.x * blockDim.x + threadIdx.x;   // 512*256
    if (idx >= 512 * 256) return;
    int p = idx & 255, n = idx >> 8;
    float w0 = W[(long long)(2 * p) * 512 + n];
    float w1 = W[(long long)(2 * p + 1) * 512 + n];
    uint32_t l; uint32_t hh = pack_split(w0, w1, l);
    hi[idx] = hh; lo[idx] = l;
}

__global__ void out_pack_kernel(const float* __restrict__ W_mean, const float* __restrict__ W_logstd,
                                const float* __restrict__ b_mean, const float* __restrict__ b_logstd,
                                uint32_t* __restrict__ hi, uint32_t* __restrict__ lo,
                                float* __restrict__ bout)
{
    int idx = blockIdx.x * blockDim.x + threadIdx.x;   // 128*256
    if (idx >= 128 * 256) return;
    int p = idx & 255, n = idx >> 8;
    const float* W = (n < 64) ? W_mean : W_logstd;
    int j = n & 63;
    float w0 = W[(long long)(2 * p) * 64 + j];
    float w1 = W[(long long)(2 * p + 1) * 64 + j];
    uint32_t l; uint32_t hh = pack_split(w0, w1, l);
    hi[idx] = hh; lo[idx] = l;
    if (p == 0) bout[n] = (n < 64) ? b_mean[j] : b_logstd[j];
}

// ---------------------------------------------------------------------------
// Split tensor-core GEMM, CTA tile 128 x TN, 8 warps x (64 x TN/4).
//   ASRC: 0 = A fp32 (bf16-split on the fly), 1 = A pre-split hi/lo planes [M][K/2]
//   ACT : 0 none, 1 leaky, 2 relu, 3 kv-mode (leaky iff col>=512), 4 out-split+clip
//   OUTM: 0 = fp32 C, 1 = bf16 hi/lo planes, 2 = fp16 hi/lo planes
//   BSP : 2 = B bf16 hi/lo planes, 3 MMAs/k16 ; 1 = B single fp16 plane, 2 MMAs/k16
// R9-proven register double-buffer mainloop.
// ---------------------------------------------------------------------------
template <int ACT, int OUTM, int ASRC, int TN, int BSP>
__global__ __launch_bounds__(256, 1)
void mma_gemm_kernel(const float* __restrict__ Af,
                     const uint32_t* __restrict__ AhiG, const uint32_t* __restrict__ AloG,
                     const uint32_t* __restrict__ BhiG, const uint32_t* __restrict__ BloG,
                     const float* __restrict__ biasg,
                     float* __restrict__ Cf,
                     uint32_t* __restrict__ ChiG, uint32_t* __restrict__ CloG,
                     int M, int N, int K,
                     long long sA, long long sBw, long long sBias, long long sC)
{
    constexpr int ASZ = 128 * 12;          // words per A plane
    constexpr int BSZ = TN * 12;           // words per B plane
    constexpr int NBPL = (BSP == 2) ? 2 : 1;            // B planes
    constexpr int BUFW = 2 * ASZ + NBPL * BSZ;
    constexpr int WNT = TN / 4;            // warp n-tile
    constexpr int NJ = WNT / 8;            // n8 tiles per warp
    constexpr int NB = WNT / 16;           // LDSM.x4 per B plane per warp
    constexpr int RB = (BSP == 2) ? (TN / 128) : (TN / 256);  // B rows per thread

    extern __shared__ uint32_t sm[];

    const int bz = blockIdx.z;
    const float* Ab = (ASRC == 0) ? (Af + bz * sA) : nullptr;
    const uint32_t* AhB = (ASRC == 1) ? (AhiG + bz * sA) : nullptr;
    const uint32_t* AlB = (ASRC == 1) ? (AloG + bz * sA) : nullptr;
    const uint32_t* BhB = BhiG + bz * sBw;
    const uint32_t* BlB = (BSP == 2) ? (BloG + bz * sBw) : nullptr;
    const float* bias = biasg ? (biasg + bz * sBias) : nullptr;
    float* C = Cf ? (Cf + bz * sC) : nullptr;
    uint32_t* Chi = ChiG ? (ChiG + bz * sC) : nullptr;
    uint32_t* Clo = CloG ? (CloG + bz * sC) : nullptr;

    const int t = threadIdx.x;
    const int lane = t & 31;
    const int warp = t >> 5;
    const int wm = warp >> 2;           // 0..1
    const int wn = warp & 3;            // 0..3
    const int m0 = blockIdx.y * 128;
    const int n0 = blockIdx.x * TN;
    const int Kw = K >> 1;

    // staging roles
    const int am = t >> 1;              // A row 0..127
    const int ak = t & 1;               // A k-half
    const int bpl = (BSP == 2) ? (t >> 7) : 0;          // B plane
    const int bn0 = (BSP == 2) ? ((t & 127) * RB) : (t * RB);  // B first row

    float acc[4][NJ][4];
    #pragma unroll
    for (int i = 0; i < 4; ++i)
        #pragma unroll
        for (int j = 0; j < NJ; ++j)
            #pragma unroll
            for (int q = 0; q < 4; ++q) acc[i][j][q] = 0.f;

    const uint32_t sbase = (uint32_t)__cvta_generic_to_shared(sm);
    const uint32_t aoff = (((uint32_t)(wm * 64 + (lane & 15)) * 12 + (lane >> 4) * 4)) * 4;
    const uint32_t boff = (((uint32_t)(wn * WNT + (lane & 7) + ((lane >> 4) & 1) * 8) * 12
                            + ((lane >> 3) & 1) * 4)) * 4;

    const float* aptrf = (ASRC == 0) ? (Ab + (long long)(m0 + am) * K + ak * 8) : nullptr;
    const uint32_t* ahptr = (ASRC == 1) ? (AhB + (long long)(m0 + am) * Kw + ak * 4) : nullptr;
    const uint32_t* alptr = (ASRC == 1) ? (AlB + (long long)(m0 + am) * Kw + ak * 4) : nullptr;
    const uint32_t* bptr = ((BSP == 2 && bpl) ? BlB : BhB) + (long long)(n0 + bn0) * Kw;

    uint32_t* aS_h = sm + am * 12 + ak * 4;                 // + buf*BUFW
    uint32_t* aS_l = aS_h + ASZ;
    uint32_t* bS = sm + 2 * ASZ + bpl * BSZ + bn0 * 12;

    float4 av0, av1;
    uint4 ahv, alv;
    uint4 bv[RB][2];

    auto load_chunk = [&](int k0) {
        if (ASRC == 0) {
            av0 = *(const float4*)(aptrf + k0);
            av1 = *(const float4*)(aptrf + k0 + 4);
        } else {
            ahv = *(const uint4*)(ahptr + (k0 >> 1));
            alv = *(const uint4*)(alptr + (k0 >> 1));
        }
        #pragma unroll
        for (int r = 0; r < RB; ++r) {
            bv[r][0] = *(const uint4*)(bptr + (long long)r * Kw + (k0 >> 1));
            bv[r][1] = *(const uint4*)(bptr + (long long)r * Kw + (k0 >> 1) + 4);
        }
    };

    auto store_smem = [&](int buf) {
        if (ASRC == 0) {
            float v[8] = {av0.x, av0.y, av0.z, av0.w, av1.x, av1.y, av1.z, av1.w};
            uint32_t hi[4], lo[4];
            #pragma unroll
            for (int j = 0; j < 4; ++j) hi[j] = pack_split(v[2 * j], v[2 * j + 1], lo[j]);
            *(uint4*)(aS_h + buf * BUFW) = make_uint4(hi[0], hi[1], hi[2], hi[3]);
            *(uint4*)(aS_l + buf * BUFW) = make_uint4(lo[0], lo[1], lo[2], lo[3]);
        } else {
            *(uint4*)(aS_h + buf * BUFW) = ahv;
            *(uint4*)(aS_l + buf * BUFW) = alv;
        }
        #pragma unroll
        for (int r = 0; r < RB; ++r) {
            *(uint4*)(bS + buf * BUFW + r * 12) = bv[r][0];
            *(uint4*)(bS + buf * BUFW + r * 12 + 4) = bv[r][1];
        }
    };

    auto mma_step = [&](int buf) {
        const uint32_t b0 = sbase + (uint32_t)buf * (BUFW * 4);
        uint32_t AH[4][4], AL[4][4], BH[NB][4], BL[(BSP == 2) ? NB : 1][4];
        #pragma unroll
        for (int i = 0; i < 4; ++i) {
            LDSM_X4(AH[i], b0 + aoff + i * (16 * 12 * 4));
            LDSM_X4(AL[i], b0 + ASZ * 4 + aoff + i * (16 * 12 * 4));
        }
        #pragma unroll
        for (int j = 0; j < NB; ++j) {
            LDSM_X4(BH[j], b0 + 2 * ASZ * 4 + boff + j * (16 * 12 * 4));
            if (BSP == 2)
                LDSM_X4(BL[j], b0 + 2 * ASZ * 4 + BSZ * 4 + boff + j * (16 * 12 * 4));
        }
        #pragma unroll
        for (int i = 0; i < 4; ++i)
            #pragma unroll
            for (int jj = 0; jj < NJ; ++jj) {
                const int jm = jj >> 1, js = (jj & 1) * 2;
                if (BSP == 2) {
                    MMA_BF16(acc[i][jj], AH[i], BH[jm][js], BH[jm][js + 1]);
                    MMA_BF16(acc[i][jj], AH[i], BL[jm][js], BL[jm][js + 1]);
                    MMA_BF16(acc[i][jj], AL[i], BH[jm][js], BH[jm][js + 1]);
                } else {
                    MMA_F16(acc[i][jj], AH[i], BH[jm][js], BH[jm][js + 1]);
                    MMA_F16(acc[i][jj], AL[i], BH[jm][js], BH[jm][js + 1]);
                }
            }
    };

    load_chunk(0);
    store_smem(0);
    __syncthreads();
    int buf = 0;
    for (int k0 = 16; k0 < K; k0 += 16) {
        load_chunk(k0);
        mma_step(buf);
        store_smem(buf ^ 1);
        __syncthreads();
        buf ^= 1;
    }
    mma_step(buf);

    // ---- epilogue ----
    const int g = lane >> 2, tq = lane & 3;
    const int Nw = N >> 1;
    #pragma unroll
    for (int i = 0; i < 4; ++i) {
        const int row = m0 + wm * 64 + i * 16 + g;
        #pragma unroll
        for (int jj = 0; jj < NJ; ++jj) {
            const int col = n0 + wn * WNT + jj * 8 + tq * 2;
            float b0v = bias ? bias[col] : 0.f;
            float b1v = bias ? bias[col + 1] : 0.f;
            float v00 = acc[i][jj][0] + b0v, v01 = acc[i][jj][1] + b1v;
            float v10 = acc[i][jj][2] + b0v, v11 = acc[i][jj][3] + b1v;
            if (ACT == 1) {
                v00 = v00 >= 0.f ? v00 : 0.01f * v00;
                v01 = v01 >= 0.f ? v01 : 0.01f * v01;
                v10 = v10 >= 0.f ? v10 : 0.01f * v10;
                v11 = v11 >= 0.f ? v11 : 0.01f * v11;
            } else if (ACT == 2) {
                v00 = fmaxf(v00, 0.f); v01 = fmaxf(v01, 0.f);
                v10 = fmaxf(v10, 0.f); v11 = fmaxf(v11, 0.f);
            } else if (ACT == 3) {
                if (col >= 512) {
                    v00 = v00 >= 0.f ? v00 : 0.01f * v00;
                    v01 = v01 >= 0.f ? v01 : 0.01f * v01;
                    v10 = v10 >= 0.f ? v10 : 0.01f * v10;
                    v11 = v11 >= 0.f ? v11 : 0.01f * v11;
                }
            }
            if (ACT == 4) {
                const long long base2 = (long long)M * 64;
                float vv[4] = {v00, v01, v10, v11};
                int rr[4] = {row, row, row + 8, row + 8};
                int cc[4] = {col, col + 1, col, col + 1};
                #pragma unroll
                for (int q = 0; q < 4; ++q) {
                    if (cc[q] < 64) {
                        C[(long long)rr[q] * 64 + cc[q]] = vv[q];
                    } else {
                        float x = fminf(fmaxf(vv[q], -20.f), 2.f);
                        C[base2 + (long long)rr[q] * 64 + (cc[q] - 64)] = x;
                    }
                }
            } else if (OUTM == 1 || OUTM == 2) {
                uint32_t l0, l1, h0, h1;
                if (OUTM == 1) {
                    h0 = pack_split(v00, v01, l0);
                    h1 = pack_split(v10, v11, l1);
                } else {
                    h0 = pack_split_f16(v00, v01, l0);
                    h1 = pack_split_f16(v10, v11, l1);
                }
                Chi[(long long)row * Nw + (col >> 1)] = h0;
                Clo[(long long)row * Nw + (col >> 1)] = l0;
                Chi[(long long)(row + 8) * Nw + (col >> 1)] = h1;
                Clo[(long long)(row + 8) * Nw + (col >> 1)] = l1;
            } else {
                *(float2*)&C[(long long)row * N + col] = make_float2(v00, v01);
                *(float2*)&C[(long long)(row + 8) * N + col] = make_float2(v10, v11);
            }
        }
    }
}

// ---------------------------------------------------------------------------
// Attention over KV [e][b][1024] (keys 0..511, vals 512..1023); sel fp32.
// ---------------------------------------------------------------------------
__global__ void attn_kernel(const float* __restrict__ KV, const float* __restrict__ sel,
                            float* __restrict__ actor_in,
                            uint32_t* __restrict__ ain_hi, uint32_t* __restrict__ ain_lo)
{
    const int b = blockIdx.x;
    const int a = threadIdx.x >> 5;
    const int lane = threadIdx.x & 31;
    const int colbase = a * 64 + lane * 2;

    const float2 s2 = *reinterpret_cast<const float2*>(&sel[(long long)b * AD + colbase]);

    float v0[E], v1[E], logit[E];
    #pragma unroll
    for (int e = 0; e < E; ++e) {
        long long off = ((long long)e * Bb + b) * 1024 + colbase;
        float2 k2 = *reinterpret_cast<const float2*>(&KV[off]);
        float2 vv = *reinterpret_cast<const float2*>(&KV[off + 512]);
        v0[e] = vv.x; v1[e] = vv.y;
        float p = s2.x * k2.x + s2.y * k2.y;
        #pragma unroll
        for (int o = 16; o >= 1; o >>= 1) p += __shfl_xor_sync(0xffffffffu, p, o);
        logit[e] = p * 0.125f;
    }
    float mx = logit[0];
    #pragma unroll
    for (int e = 1; e < E; ++e) mx = fmaxf(mx, logit[e]);
    float den = 0.f, w[E];
    #pragma unroll
    for (int e = 0; e < E; ++e) { w[e] = __expf(logit[e] - mx); den += w[e]; }
    float inv = 1.f / den;
    float a0 = 0.f, a1 = 0.f;
    #pragma unroll
    for (int e = 0; e < E; ++e) {
        float we = w[e] * inv;
        a0 += we * v0[e];
        a1 += we * v1[e];
    }
    *reinterpret_cast<float2*>(&actor_in[(long long)b * AD + colbase]) = make_float2(a0, a1);
    uint32_t l; uint32_t h = pack_split(a0, a1, l);
    long long po = (long long)b * 256 + (colbase >> 1);
    ain_hi[po] = h;
    ain_lo[po] = l;
}

// ---------------------------------------------------------------------------
// Launch
// ---------------------------------------------------------------------------
constexpr int SM_BSP2_256 = (2 * 128 * 12 + 2 * 256 * 12) * 2 * 4;   // 73728
constexpr int SM_BSP1_256 = (2 * 128 * 12 + 1 * 256 * 12) * 2 * 4;   // 49152
constexpr int SM_BSP2_128 = (2 * 128 * 12 + 2 * 128 * 12) * 2 * 4;   // 49152

extern "C" void kernel_launch(void* const* d_in, const int* in_sizes, int n_in,
                              void* d_out, int out_size)
{
    float* S = nullptr;
    cudaGetSymbolAddress((void**)&S, g_scratch);
    uint32_t* Su = (uint32_t*)S;

    const float* states      = (const float*)d_in[0];
    const float* pre_actions = (const float*)d_in[1];
    const float* W_enc       = (const float*)d_in[2];
    const float* b_enc       = (const float*)d_in[3];
    const float* W_pre       = (const float*)d_in[4];
    const float* b_pre       = (const float*)d_in[5];
    const float* Wk          = (const float*)d_in[6];
    const float* Wsel        = (const float*)d_in[7];
    const float* Wv          = (const float*)d_in[8];
    const float* bv          = (const float*)d_in[9];
    const float* W_actor     = (const float*)d_in[10];
    const float* b_actor     = (const float*)d_in[11];
    const float* W_mean      = (const float*)d_in[12];
    const float* b_mean      = (const float*)d_in[13];
    const float* W_logstd    = (const float*)d_in[14];
    const float* b_logstd    = (const float*)d_in[15];

    float* out = (float*)d_out;
    float* actor_in = out + 2LL * Bb * 64;   // third output region

    cudaFuncSetAttribute(mma_gemm_kernel<1, 2, 0, 256, 2>, cudaFuncAttributeMaxDynamicSharedMemorySize, SM_BSP2_256);
    cudaFuncSetAttribute(mma_gemm_kernel<3, 0, 1, 256, 1>, cudaFuncAttributeMaxDynamicSharedMemorySize, SM_BSP1_256);
    cudaFuncSetAttribute(mma_gemm_kernel<1, 1, 0, 256, 2>, cudaFuncAttributeMaxDynamicSharedMemorySize, SM_BSP2_256);
    cudaFuncSetAttribute(mma_gemm_kernel<0, 0, 1, 256, 2>, cudaFuncAttributeMaxDynamicSharedMemorySize, SM_BSP2_256);
    cudaFuncSetAttribute(mma_gemm_kernel<2, 1, 1, 256, 2>, cudaFuncAttributeMaxDynamicSharedMemorySize, SM_BSP2_256);
    cudaFuncSetAttribute(mma_gemm_kernel<4, 0, 1, 128, 2>, cudaFuncAttributeMaxDynamicSharedMemorySize, SM_BSP2_128);

    // ---- prep (parallel, tiny) ----
    bn_partial_kernel<<<dim3(16, E), 256>>>(states, S + OFF_SUMS);
    bn_final_kernel<<<2, 256>>>(S + OFF_SUMS, S + OFF_MU, S + OFF_RSTD);
    enc_fold_kernel<<<512, 256>>>(W_enc, b_enc, S + OFF_MU, S + OFF_RSTD,
                                  Su + OFF_EHI, Su + OFF_ELO, S + OFF_BP);
    kv_pack_kernel<<<1024, 256>>>(Wk, Wv, bv, Su + OFF_KVHI, S + OFF_KVB);
    sel_pack_kernel<<<512, 256>>>(Wsel, Su + OFF_SELHI, Su + OFF_SELLO);
    mat_split_kernel<<<512, 256>>>(W_pre, Su + OFF_PREHI, Su + OFF_PRELO);
    mat_split_kernel<<<512, 256>>>(W_actor, Su + OFF_ACTHI, Su + OFF_ACTLO);
    out_pack_kernel<<<128, 256>>>(W_mean, W_logstd, b_mean, b_logstd,
                                  Su + OFF_OHI, Su + OFF_OLO, S + OFF_BOUT);

    // ---- encoder: enc fp16 planes = leaky(states @ Wenc' + bp)   A fp32, bf16 B ----
    mma_gemm_kernel<1, 2, 0, 256, 2><<<dim3(2, 128, E), 256, SM_BSP2_256>>>(
        states, nullptr, nullptr, Su + OFF_EHI, Su + OFF_ELO, S + OFF_BP,
        nullptr, Su + OFF_ENCH, Su + OFF_ENCL,
        Bb, H, Nn,
        (long long)Bb * Nn, 512LL * 32, 512LL, (long long)Bb * 256);

    // ---- fused keys|vals: KV = encs @ [Wk|Wv] (fp16 2-term, 2 MMAs/k16) ----
    mma_gemm_kernel<3, 0, 1, 256, 1><<<dim3(4, 128, E), 256, SM_BSP1_256>>>(
        nullptr, Su + OFF_ENCH, Su + OFF_ENCL, Su + OFF_KVHI, nullptr, S + OFF_KVB,
        S + OFF_KV, nullptr, nullptr,
        Bb, 1024, H,
        (long long)Bb * 256, 0LL, 0LL, (long long)Bb * 1024);

    // ---- pre bf16 planes = leaky(pre_actions @ W_pre + b_pre) ----
    mma_gemm_kernel<1, 1, 0, 256, 2><<<dim3(2, 128, 1), 256, SM_BSP2_256>>>(
        pre_actions, nullptr, nullptr, Su + OFF_PREHI, Su + OFF_PRELO, b_pre,
        nullptr, Su + OFF_PREH, Su + OFF_PREL,
        Bb, H, H, 0LL, 0LL, 0LL, 0LL);

    // ---- sel = pre @ Wsel ----
    mma_gemm_kernel<0, 0, 1, 256, 2><<<dim3(2, 128, 1), 256, SM_BSP2_256>>>(
        nullptr, Su + OFF_PREH, Su + OFF_PREL, Su + OFF_SELHI, Su + OFF_SELLO, nullptr,
        S + OFF_SEL, nullptr, nullptr,
        Bb, AD, H, 0LL, 0LL, 0LL, 0LL);

    // ---- attention -> actor_in fp32 (d_out) + bf16 planes ----
    attn_kernel<<<Bb, 256>>>(S + OFF_KV, S + OFF_SEL, actor_in,
                             Su + OFF_AINH, Su + OFF_AINL);

    // ---- x bf16 planes = relu(actor_in @ W_actor + b_actor) ----
    mma_gemm_kernel<2, 1, 1, 256, 2><<<dim3(2, 128, 1), 256, SM_BSP2_256>>>(
        nullptr, Su + OFF_AINH, Su + OFF_AINL, Su + OFF_ACTHI, Su + OFF_ACTLO, b_actor,
        nullptr, Su + OFF_XH, Su + OFF_XL,
        Bb, H, H, 0LL, 0LL, 0LL, 0LL);

    // ---- fused output GEMM: [mean | clip(logstd)] -> d_out ----
    mma_gemm_kernel<4, 0, 1, 128, 2><<<dim3(1, 128, 1), 256, SM_BSP2_128>>>(
        nullptr, Su + OFF_XH, Su + OFF_XL, Su + OFF_OHI, Su + OFF_OLO, S + OFF_BOUT,
        out, nullptr, nullptr,
        Bb, 128, H, 0LL, 0LL, 0LL, 0LL);
}

// round 13
// speedup vs baseline: 1.5059x; 1.2422x over previous
#include <cuda_runtime.h>
#include <cuda_bf16.h>
#include <cuda_fp16.h>
#include <cstdint>

// ---------------------------------------------------------------------------
// Problem constants
// ---------------------------------------------------------------------------
constexpr int E  = 8;
constexpr int Bb = 16384;
constexpr int Nn = 64;
constexpr int H  = 512;
constexpr int AD = 512;            // A*D

// ---------------------------------------------------------------------------
// Scratch layout (4-byte words)
// ---------------------------------------------------------------------------
constexpr long long OFF_SUMS  = 0;                          // 16384
constexpr long long OFF_MU    = OFF_SUMS  + 16384;          // 512
constexpr long long OFF_RSTD  = OFF_MU    + 512;            // 512
constexpr long long OFF_BP    = OFF_RSTD  + 512;            // 4096
constexpr long long OFF_KVB   = OFF_BP    + 4096;           // 1024
constexpr long long OFF_BOUT  = OFF_KVB   + 1024;           // 128
// weight planes
constexpr long long OFF_EHI   = OFF_BOUT  + 128;            // E*512*32 = 131072
constexpr long long OFF_ELO   = OFF_EHI   + 131072;
constexpr long long OFF_KVHI  = OFF_ELO   + 131072;         // 1024*256 (single fp16 plane)
constexpr long long OFF_KVLO  = OFF_KVHI  + 262144;         // (unused)
constexpr long long OFF_SELHI = OFF_KVLO  + 262144;         // 512*256 (single fp16 plane)
constexpr long long OFF_SELLO = OFF_SELHI + 131072;         // (unused)
constexpr long long OFF_PREHI = OFF_SELLO + 131072;
constexpr long long OFF_PRELO = OFF_PREHI + 131072;
constexpr long long OFF_ACTHI = OFF_PRELO + 131072;
constexpr long long OFF_ACTLO = OFF_ACTHI + 131072;
constexpr long long OFF_OHI   = OFF_ACTLO + 131072;         // 128*256
constexpr long long OFF_OLO   = OFF_OHI   + 32768;
// activation planes / buffers
constexpr long long OFF_ENCH  = OFF_OLO   + 32768;          // E*B*256 (fp16 hi)
constexpr long long OFF_ENCL  = OFF_ENCH  + 33554432LL;     // (fp16 lo)
constexpr long long OFF_KV    = OFF_ENCL  + 33554432LL;     // E*B*1024 fp32
constexpr long long OFF_PREH  = OFF_KV    + 134217728LL;    // B*256 (fp16 hi)
constexpr long long OFF_PREL  = OFF_PREH  + 4194304LL;      // (fp16 lo)
constexpr long long OFF_SEL   = OFF_PREL  + 4194304LL;      // B*512 fp32
constexpr long long OFF_AINH  = OFF_SEL   + 8388608LL;      // B*256 (bf16)
constexpr long long OFF_AINL  = OFF_AINH  + 4194304LL;
constexpr long long OFF_XH    = OFF_AINL  + 4194304LL;      // B*256 (bf16)
constexpr long long OFF_XL    = OFF_XH    + 4194304LL;
constexpr long long SCRATCH_TOTAL = OFF_XL + 4194304LL;     // ~944 MB

__device__ __align__(256) float g_scratch[SCRATCH_TOTAL];

// ---------------------------------------------------------------------------
// Helpers
// ---------------------------------------------------------------------------
__device__ __forceinline__ uint32_t pack_split(float x, float y, uint32_t& lo)
{
    __nv_bfloat16 hx = __float2bfloat16_rn(x);
    __nv_bfloat16 hy = __float2bfloat16_rn(y);
    float rx = x - __bfloat162float(hx);
    float ry = y - __bfloat162float(hy);
    __nv_bfloat16 lx = __float2bfloat16_rn(rx);
    __nv_bfloat16 ly = __float2bfloat16_rn(ry);
    lo = (uint32_t)__bfloat16_as_ushort(lx) | ((uint32_t)__bfloat16_as_ushort(ly) << 16);
    return (uint32_t)__bfloat16_as_ushort(hx) | ((uint32_t)__bfloat16_as_ushort(hy) << 16);
}

__device__ __forceinline__ uint32_t pack_split_f16(float x, float y, uint32_t& lo)
{
    __half hx = __float2half_rn(x);
    __half hy = __float2half_rn(y);
    float rx = x - __half2float(hx);
    float ry = y - __half2float(hy);
    __half lx = __float2half_rn(rx);
    __half ly = __float2half_rn(ry);
    lo = (uint32_t)__half_as_ushort(lx) | ((uint32_t)__half_as_ushort(ly) << 16);
    return (uint32_t)__half_as_ushort(hx) | ((uint32_t)__half_as_ushort(hy) << 16);
}

__device__ __forceinline__ uint32_t pack_f16(float x, float y)
{
    __half hx = __float2half_rn(x);
    __half hy = __float2half_rn(y);
    return (uint32_t)__half_as_ushort(hx) | ((uint32_t)__half_as_ushort(hy) << 16);
}

#define MMA_BF16(d, a, b0v, b1v)                                              \
    asm volatile("mma.sync.aligned.m16n8k16.row.col.f32.bf16.bf16.f32 "       \
                 "{%0,%1,%2,%3}, {%4,%5,%6,%7}, {%8,%9}, {%0,%1,%2,%3};"      \
                 : "+f"(d[0]), "+f"(d[1]), "+f"(d[2]), "+f"(d[3])             \
                 : "r"(a[0]), "r"(a[1]), "r"(a[2]), "r"(a[3]),                \
                   "r"(b0v), "r"(b1v))

#define MMA_F16(d, a, b0v, b1v)                                               \
    asm volatile("mma.sync.aligned.m16n8k16.row.col.f32.f16.f16.f32 "         \
                 "{%0,%1,%2,%3}, {%4,%5,%6,%7}, {%8,%9}, {%0,%1,%2,%3};"      \
                 : "+f"(d[0]), "+f"(d[1]), "+f"(d[2]), "+f"(d[3])             \
                 : "r"(a[0]), "r"(a[1]), "r"(a[2]), "r"(a[3]),                \
                   "r"(b0v), "r"(b1v))

#define LDSM_X4(r, addr)                                                      \
    asm volatile("ldmatrix.sync.aligned.m8n8.x4.shared.b16 {%0,%1,%2,%3}, [%4];" \
                 : "=r"(r[0]), "=r"(r[1]), "=r"(r[2]), "=r"(r[3]) : "r"(addr))

// ---------------------------------------------------------------------------
// BatchNorm stats
// ---------------------------------------------------------------------------
__global__ void bn_partial_kernel(const float* __restrict__ states, float* __restrict__ partial)
{
    int c = blockIdx.x, e = blockIdx.y, t = threadIdx.x;
    int n = t & 63, r0 = t >> 6;
    const float* sp = states + (long long)e * Bb * Nn;
    long long b = (long long)c * 1024 + r0;
    float s1 = 0.f, s2 = 0.f;
    #pragma unroll 4
    for (int it = 0; it < 256; ++it) {
        float v = sp[(b + (long long)it * 4) * Nn + n];
        s1 += v; s2 += v * v;
    }
    __shared__ float sh1[256], sh2[256];
    sh1[t] = s1; sh2[t] = s2;
    __syncthreads();
    if (t < 64) {
        float a1 = sh1[t] + sh1[t + 64] + sh1[t + 128] + sh1[t + 192];
        float a2 = sh2[t] + sh2[t + 64] + sh2[t + 128] + sh2[t + 192];
        long long base = ((long long)e * 16 + c) * 64 + t;
        partial[base] = a1;
        partial[8192 + base] = a2;
    }
}

__global__ void bn_final_kernel(const float* __restrict__ partial,
                                float* __restrict__ mu, float* __restrict__ rstd)
{
    int idx = blockIdx.x * blockDim.x + threadIdx.x;
    if (idx >= E * Nn) return;
    int e = idx >> 6, n = idx & 63;
    float s1 = 0.f, s2 = 0.f;
    for (int c = 0; c < 16; ++c) {
        long long base = ((long long)e * 16 + c) * 64 + n;
        s1 += partial[base];
        s2 += partial[8192 + base];
    }
    float m = s1 * (1.f / Bb);
    float var = s2 * (1.f / Bb) - m * m;
    mu[idx] = m;
    rstd[idx] = rsqrtf(var + 1e-5f);
}

// ---------------------------------------------------------------------------
// Merged encoder fold: BN-folded weight split (bf16 planes) + bias
// ---------------------------------------------------------------------------
__global__ void enc_fold_kernel(const float* __restrict__ W_enc, const float* __restrict__ b_enc,
                                const float* __restrict__ mu, const float* __restrict__ rstd,
                                uint32_t* __restrict__ hi, uint32_t* __restrict__ lo,
                                float* __restrict__ bp)
{
    int idx = blockIdx.x * blockDim.x + threadIdx.x;   // E*H*32
    if (idx >= E * H * 32) return;
    int h = idx & 511;
    int rest = idx >> 9;
    int p = rest & 31;
    int e = rest >> 5;
    int k = 2 * p;
    float w0 = rstd[e * 64 + k]     * W_enc[((long long)e * 64 + k) * H + h];
    float w1 = rstd[e * 64 + k + 1] * W_enc[((long long)e * 64 + k + 1) * H + h];
    uint32_t l; uint32_t hh = pack_split(w0, w1, l);
    long long o = ((long long)e * 512 + h) * 32 + p;
    hi[o] = hh; lo[o] = l;
    if (p == 0) {
        float bacc = b_enc[e * H + h];
        #pragma unroll 8
        for (int n = 0; n < Nn; ++n)
            bacc -= mu[e * 64 + n] * rstd[e * 64 + n] * W_enc[((long long)e * 64 + n) * H + h];
        bp[e * H + h] = bacc;
    }
}

// ---------------------------------------------------------------------------
// KV weights: single plain-fp16 plane [1024][256 words]
// ---------------------------------------------------------------------------
__global__ void kv_pack_kernel(const float* __restrict__ Wk, const float* __restrict__ Wv,
                               const float* __restrict__ bv,
                               uint32_t* __restrict__ wplane, float* __restrict__ kvbias)
{
    int idx = blockIdx.x * blockDim.x + threadIdx.x;   // 1024*256
    if (idx >= 1024 * 256) return;
    int p = idx & 255, n = idx >> 8;
    bool isv = n >= 512;
    int a = (n & 511) >> 6, dd = n & 63;
    const float* W = isv ? Wv : Wk;
    int k = 2 * p;
    float w0 = W[((long long)a * H + k) * 64 + dd];
    float w1 = W[((long long)a * H + k + 1) * 64 + dd];
    wplane[idx] = pack_f16(w0, w1);
    if (p == 0) kvbias[n] = isv ? bv[n - 512] : 0.f;
}

// Wsel: single plain-fp16 plane [512][256 words]
__global__ void sel_pack_kernel(const float* __restrict__ Wsel, uint32_t* __restrict__ wplane)
{
    int idx = blockIdx.x * blockDim.x + threadIdx.x;   // 512*256
    if (idx >= 512 * 256) return;
    int p = idx & 255, n = idx >> 8;
    int a = n >> 6, dd = n & 63;
    int k = 2 * p;
    float w0 = Wsel[((long long)a * H + k) * 64 + dd];
    float w1 = Wsel[((long long)a * H + k + 1) * 64 + dd];
    wplane[idx] = pack_f16(w0, w1);
}

__global__ void mat_split_kernel(const float* __restrict__ W,   // [512][512] k x n
                                 uint32_t* __restrict__ hi, uint32_t* __restrict__ lo)
{
    int idx = blockIdx.x * blockDim.x + threadIdx.x;   // 512*256
    if (idx >= 512 * 256) return;
    int p = idx & 255, n = idx >> 8;
    float w0 = W[(long long)(2 * p) * 512 + n];
    float w1 = W[(long long)(2 * p + 1) * 512 + n];
    uint32_t l; uint32_t hh = pack_split(w0, w1, l);
    hi[idx] = hh; lo[idx] = l;
}

__global__ void out_pack_kernel(const float* __restrict__ W_mean, const float* __restrict__ W_logstd,
                                const float* __restrict__ b_mean, const float* __restrict__ b_logstd,
                                uint32_t* __restrict__ hi, uint32_t* __restrict__ lo,
                                float* __restrict__ bout)
{
    int idx = blockIdx.x * blockDim.x + threadIdx.x;   // 128*256
    if (idx >= 128 * 256) return;
    int p = idx & 255, n = idx >> 8;
    const float* W = (n < 64) ? W_mean : W_logstd;
    int j = n & 63;
    float w0 = W[(long long)(2 * p) * 64 + j];
    float w1 = W[(long long)(2 * p + 1) * 64 + j];
    uint32_t l; uint32_t hh = pack_split(w0, w1, l);
    hi[idx] = hh; lo[idx] = l;
    if (p == 0) bout[n] = (n < 64) ? b_mean[j] : b_logstd[j];
}

// ---------------------------------------------------------------------------
// Split tensor-core GEMM, CTA tile 128 x TN, 8 warps x (64 x TN/4).
//   ASRC: 0 = A fp32 (bf16-split on the fly), 1 = A pre-split planes [M][K/2]
//   ACT : 0 none, 1 leaky, 2 relu, 3 kv-mode (leaky iff col>=512), 4 out-split+clip
//   OUTM: 0 = fp32 C, 1 = bf16 hi/lo planes, 2 = fp16 hi/lo planes
//   BSP : 2 = B bf16 hi/lo planes (bf16 MMA) ; 1 = B single fp16 plane (fp16 MMA)
//   ATRM: A terms used in MMA: 2 = hi+lo ; 1 = hi only (requires ASRC=1, BSP=1)
// MMAs per k16: BSP2 -> 3 (AH*BH, AH*BL, AL*BH); BSP1 -> ATRM.
// ---------------------------------------------------------------------------
template <int ACT, int OUTM, int ASRC, int TN, int BSP, int ATRM>
__global__ __launch_bounds__(256, 1)
void mma_gemm_kernel(const float* __restrict__ Af,
                     const uint32_t* __restrict__ AhiG, const uint32_t* __restrict__ AloG,
                     const uint32_t* __restrict__ BhiG, const uint32_t* __restrict__ BloG,
                     const float* __restrict__ biasg,
                     float* __restrict__ Cf,
                     uint32_t* __restrict__ ChiG, uint32_t* __restrict__ CloG,
                     int M, int N, int K,
                     long long sA, long long sBw, long long sBias, long long sC)
{
    constexpr int ASZ = 128 * 12;          // words per A plane
    constexpr int BSZ = TN * 12;           // words per B plane
    constexpr int NBPL = (BSP == 2) ? 2 : 1;            // B planes
    constexpr int BUFW = ATRM * ASZ + NBPL * BSZ;
    constexpr int WNT = TN / 4;            // warp n-tile
    constexpr int NJ = WNT / 8;            // n8 tiles per warp
    constexpr int NB = WNT / 16;           // LDSM.x4 per B plane per warp
    constexpr int RB = (BSP == 2) ? (TN / 128) : (TN / 256);  // B rows per thread

    extern __shared__ uint32_t sm[];

    const int bz = blockIdx.z;
    const float* Ab = (ASRC == 0) ? (Af + bz * sA) : nullptr;
    const uint32_t* AhB = (ASRC == 1) ? (AhiG + bz * sA) : nullptr;
    const uint32_t* AlB = (ASRC == 1 && ATRM == 2) ? (AloG + bz * sA) : nullptr;
    const uint32_t* BhB = BhiG + bz * sBw;
    const uint32_t* BlB = (BSP == 2) ? (BloG + bz * sBw) : nullptr;
    const float* bias = biasg ? (biasg + bz * sBias) : nullptr;
    float* C = Cf ? (Cf + bz * sC) : nullptr;
    uint32_t* Chi = ChiG ? (ChiG + bz * sC) : nullptr;
    uint32_t* Clo = CloG ? (CloG + bz * sC) : nullptr;

    const int t = threadIdx.x;
    const int lane = t & 31;
    const int warp = t >> 5;
    const int wm = warp >> 2;           // 0..1
    const int wn = warp & 3;            // 0..3
    const int m0 = blockIdx.y * 128;
    const int n0 = blockIdx.x * TN;
    const int Kw = K >> 1;

    // staging roles
    const int am = t >> 1;              // A row 0..127
    const int ak = t & 1;               // A k-half
    const int bpl = (BSP == 2) ? (t >> 7) : 0;          // B plane
    const int bn0 = (BSP == 2) ? ((t & 127) * RB) : (t * RB);  // B first row

    float acc[4][NJ][4];
    #pragma unroll
    for (int i = 0; i < 4; ++i)
        #pragma unroll
        for (int j = 0; j < NJ; ++j)
            #pragma unroll
            for (int q = 0; q < 4; ++q) acc[i][j][q] = 0.f;

    const uint32_t sbase = (uint32_t)__cvta_generic_to_shared(sm);
    const uint32_t aoff = (((uint32_t)(wm * 64 + (lane & 15)) * 12 + (lane >> 4) * 4)) * 4;
    const uint32_t boff = (((uint32_t)(wn * WNT + (lane & 7) + ((lane >> 4) & 1) * 8) * 12
                            + ((lane >> 3) & 1) * 4)) * 4;

    const float* aptrf = (ASRC == 0) ? (Ab + (long long)(m0 + am) * K + ak * 8) : nullptr;
    const uint32_t* ahptr = (ASRC == 1) ? (AhB + (long long)(m0 + am) * Kw + ak * 4) : nullptr;
    const uint32_t* alptr = (ASRC == 1 && ATRM == 2) ? (AlB + (long long)(m0 + am) * Kw + ak * 4) : nullptr;
    const uint32_t* bptr = ((BSP == 2 && bpl) ? BlB : BhB) + (long long)(n0 + bn0) * Kw;

    uint32_t* aS_h = sm + am * 12 + ak * 4;                 // + buf*BUFW
    uint32_t* aS_l = aS_h + ASZ;                            // valid iff ATRM==2
    uint32_t* bS = sm + ATRM * ASZ + bpl * BSZ + bn0 * 12;

    float4 av0, av1;
    uint4 ahv, alv;
    uint4 bv[RB][2];

    auto load_chunk = [&](int k0) {
        if (ASRC == 0) {
            av0 = *(const float4*)(aptrf + k0);
            av1 = *(const float4*)(aptrf + k0 + 4);
        } else {
            ahv = *(const uint4*)(ahptr + (k0 >> 1));
            if (ATRM == 2) alv = *(const uint4*)(alptr + (k0 >> 1));
        }
        #pragma unroll
        for (int r = 0; r < RB; ++r) {
            bv[r][0] = *(const uint4*)(bptr + (long long)r * Kw + (k0 >> 1));
            bv[r][1] = *(const uint4*)(bptr + (long long)r * Kw + (k0 >> 1) + 4);
        }
    };

    auto store_smem = [&](int buf) {
        if (ASRC == 0) {
            float v[8] = {av0.x, av0.y, av0.z, av0.w, av1.x, av1.y, av1.z, av1.w};
            uint32_t hi[4], lo[4];
            #pragma unroll
            for (int j = 0; j < 4; ++j) hi[j] = pack_split(v[2 * j], v[2 * j + 1], lo[j]);
            *(uint4*)(aS_h + buf * BUFW) = make_uint4(hi[0], hi[1], hi[2], hi[3]);
            *(uint4*)(aS_l + buf * BUFW) = make_uint4(lo[0], lo[1], lo[2], lo[3]);
        } else {
            *(uint4*)(aS_h + buf * BUFW) = ahv;
            if (ATRM == 2) *(uint4*)(aS_l + buf * BUFW) = alv;
        }
        #pragma unroll
        for (int r = 0; r < RB; ++r) {
            *(uint4*)(bS + buf * BUFW + r * 12) = bv[r][0];
            *(uint4*)(bS + buf * BUFW + r * 12 + 4) = bv[r][1];
        }
    };

    auto mma_step = [&](int buf) {
        const uint32_t b0 = sbase + (uint32_t)buf * (BUFW * 4);
        uint32_t AH[4][4], AL[(ATRM == 2) ? 4 : 1][4];
        uint32_t BH[NB][4], BL[(BSP == 2) ? NB : 1][4];
        #pragma unroll
        for (int i = 0; i < 4; ++i) {
            LDSM_X4(AH[i], b0 + aoff + i * (16 * 12 * 4));
            if (ATRM == 2)
                LDSM_X4(AL[i], b0 + ASZ * 4 + aoff + i * (16 * 12 * 4));
        }
        #pragma unroll
        for (int j = 0; j < NB; ++j) {
            LDSM_X4(BH[j], b0 + ATRM * ASZ * 4 + boff + j * (16 * 12 * 4));
            if (BSP == 2)
                LDSM_X4(BL[j], b0 + ATRM * ASZ * 4 + BSZ * 4 + boff + j * (16 * 12 * 4));
        }
        #pragma unroll
        for (int i = 0; i < 4; ++i)
            #pragma unroll
            for (int jj = 0; jj < NJ; ++jj) {
                const int jm = jj >> 1, js = (jj & 1) * 2;
                if (BSP == 2) {
                    MMA_BF16(acc[i][jj], AH[i], BH[jm][js], BH[jm][js + 1]);
                    MMA_BF16(acc[i][jj], AH[i], BL[jm][js], BL[jm][js + 1]);
                    MMA_BF16(acc[i][jj], AL[i], BH[jm][js], BH[jm][js + 1]);
                } else {
                    MMA_F16(acc[i][jj], AH[i], BH[jm][js], BH[jm][js + 1]);
                    if (ATRM == 2)
                        MMA_F16(acc[i][jj], AL[i], BH[jm][js], BH[jm][js + 1]);
                }
            }
    };

    load_chunk(0);
    store_smem(0);
    __syncthreads();
    int buf = 0;
    for (int k0 = 16; k0 < K; k0 += 16) {
        load_chunk(k0);
        mma_step(buf);
        store_smem(buf ^ 1);
        __syncthreads();
        buf ^= 1;
    }
    mma_step(buf);

    // ---- epilogue ----
    const int g = lane >> 2, tq = lane & 3;
    const int Nw = N >> 1;
    #pragma unroll
    for (int i = 0; i < 4; ++i) {
        const int row = m0 + wm * 64 + i * 16 + g;
        #pragma unroll
        for (int jj = 0; jj < NJ; ++jj) {
            const int col = n0 + wn * WNT + jj * 8 + tq * 2;
            float b0v = bias ? bias[col] : 0.f;
            float b1v = bias ? bias[col + 1] : 0.f;
            float v00 = acc[i][jj][0] + b0v, v01 = acc[i][jj][1] + b1v;
            float v10 = acc[i][jj][2] + b0v, v11 = acc[i][jj][3] + b1v;
            if (ACT == 1) {
                v00 = v00 >= 0.f ? v00 : 0.01f * v00;
                v01 = v01 >= 0.f ? v01 : 0.01f * v01;
                v10 = v10 >= 0.f ? v10 : 0.01f * v10;
                v11 = v11 >= 0.f ? v11 : 0.01f * v11;
            } else if (ACT == 2) {
                v00 = fmaxf(v00, 0.f); v01 = fmaxf(v01, 0.f);
                v10 = fmaxf(v10, 0.f); v11 = fmaxf(v11, 0.f);
            } else if (ACT == 3) {
                if (col >= 512) {
                    v00 = v00 >= 0.f ? v00 : 0.01f * v00;
                    v01 = v01 >= 0.f ? v01 : 0.01f * v01;
                    v10 = v10 >= 0.f ? v10 : 0.01f * v10;
                    v11 = v11 >= 0.f ? v11 : 0.01f * v11;
                }
            }
            if (ACT == 4) {
                const long long base2 = (long long)M * 64;
                float vv[4] = {v00, v01, v10, v11};
                int rr[4] = {row, row, row + 8, row + 8};
                int cc[4] = {col, col + 1, col, col + 1};
                #pragma unroll
                for (int q = 0; q < 4; ++q) {
                    if (cc[q] < 64) {
                        C[(long long)rr[q] * 64 + cc[q]] = vv[q];
                    } else {
                        float x = fminf(fmaxf(vv[q], -20.f), 2.f);
                        C[base2 + (long long)rr[q] * 64 + (cc[q] - 64)] = x;
                    }
                }
            } else if (OUTM == 1 || OUTM == 2) {
                uint32_t l0, l1, h0, h1;
                if (OUTM == 1) {
                    h0 = pack_split(v00, v01, l0);
                    h1 = pack_split(v10, v11, l1);
                } else {
                    h0 = pack_split_f16(v00, v01, l0);
                    h1 = pack_split_f16(v10, v11, l1);
                }
                Chi[(long long)row * Nw + (col >> 1)] = h0;
                Clo[(long long)row * Nw + (col >> 1)] = l0;
                Chi[(long long)(row + 8) * Nw + (col >> 1)] = h1;
                Clo[(long long)(row + 8) * Nw + (col >> 1)] = l1;
            } else {
                *(float2*)&C[(long long)row * N + col] = make_float2(v00, v01);
                *(float2*)&C[(long long)(row + 8) * N + col] = make_float2(v10, v11);
            }
        }
    }
}

// ---------------------------------------------------------------------------
// Attention over KV [e][b][1024] (keys 0..511, vals 512..1023); sel fp32.
// ---------------------------------------------------------------------------
__global__ void attn_kernel(const float* __restrict__ KV, const float* __restrict__ sel,
                            float* __restrict__ actor_in,
                            uint32_t* __restrict__ ain_hi, uint32_t* __restrict__ ain_lo)
{
    const int b = blockIdx.x;
    const int a = threadIdx.x >> 5;
    const int lane = threadIdx.x & 31;
    const int colbase = a * 64 + lane * 2;

    const float2 s2 = *reinterpret_cast<const float2*>(&sel[(long long)b * AD + colbase]);

    float v0[E], v1[E], logit[E];
    #pragma unroll
    for (int e = 0; e < E; ++e) {
        long long off = ((long long)e * Bb + b) * 1024 + colbase;
        float2 k2 = *reinterpret_cast<const float2*>(&KV[off]);
        float2 vv = *reinterpret_cast<const float2*>(&KV[off + 512]);
        v0[e] = vv.x; v1[e] = vv.y;
        float p = s2.x * k2.x + s2.y * k2.y;
        #pragma unroll
        for (int o = 16; o >= 1; o >>= 1) p += __shfl_xor_sync(0xffffffffu, p, o);
        logit[e] = p * 0.125f;
    }
    float mx = logit[0];
    #pragma unroll
    for (int e = 1; e < E; ++e) mx = fmaxf(mx, logit[e]);
    float den = 0.f, w[E];
    #pragma unroll
    for (int e = 0; e < E; ++e) { w[e] = __expf(logit[e] - mx); den += w[e]; }
    float inv = 1.f / den;
    float a0 = 0.f, a1 = 0.f;
    #pragma unroll
    for (int e = 0; e < E; ++e) {
        float we = w[e] * inv;
        a0 += we * v0[e];
        a1 += we * v1[e];
    }
    *reinterpret_cast<float2*>(&actor_in[(long long)b * AD + colbase]) = make_float2(a0, a1);
    uint32_t l; uint32_t h = pack_split(a0, a1, l);
    long long po = (long long)b * 256 + (colbase >> 1);
    ain_hi[po] = h;
    ain_lo[po] = l;
}

// ---------------------------------------------------------------------------
// Launch
// ---------------------------------------------------------------------------
constexpr int SM_ENC   = (2 * 128 * 12 + 2 * 256 * 12) * 2 * 4;   // 73728 (ASRC0, BSP2)
constexpr int SM_KV    = (1 * 128 * 12 + 1 * 256 * 12) * 2 * 4;   // 36864 (ATRM1, BSP1)
constexpr int SM_SEL   = (2 * 128 * 12 + 1 * 256 * 12) * 2 * 4;   // 49152 (ATRM2, BSP1)
constexpr int SM_B2    = (2 * 128 * 12 + 2 * 256 * 12) * 2 * 4;   // 73728 (BSP2 TN=256)
constexpr int SM_OUT   = (2 * 128 * 12 + 2 * 128 * 12) * 2 * 4;   // 49152 (BSP2 TN=128)

extern "C" void kernel_launch(void* const* d_in, const int* in_sizes, int n_in,
                              void* d_out, int out_size)
{
    float* S = nullptr;
    cudaGetSymbolAddress((void**)&S, g_scratch);
    uint32_t* Su = (uint32_t*)S;

    const float* states      = (const float*)d_in[0];
    const float* pre_actions = (const float*)d_in[1];
    const float* W_enc       = (const float*)d_in[2];
    const float* b_enc       = (const float*)d_in[3];
    const float* W_pre       = (const float*)d_in[4];
    const float* b_pre       = (const float*)d_in[5];
    const float* Wk          = (const float*)d_in[6];
    const float* Wsel        = (const float*)d_in[7];
    const float* Wv          = (const float*)d_in[8];
    const float* bv          = (const float*)d_in[9];
    const float* W_actor     = (const float*)d_in[10];
    const float* b_actor     = (const float*)d_in[11];
    const float* W_mean      = (const float*)d_in[12];
    const float* b_mean      = (const float*)d_in[13];
    const float* W_logstd    = (const float*)d_in[14];
    const float* b_logstd    = (const float*)d_in[15];

    float* out = (float*)d_out;
    float* actor_in = out + 2LL * Bb * 64;   // third output region

    cudaFuncSetAttribute(mma_gemm_kernel<1, 2, 0, 256, 2, 2>, cudaFuncAttributeMaxDynamicSharedMemorySize, SM_ENC);
    cudaFuncSetAttribute(mma_gemm_kernel<3, 0, 1, 256, 1, 1>, cudaFuncAttributeMaxDynamicSharedMemorySize, SM_KV);
    cudaFuncSetAttribute(mma_gemm_kernel<1, 2, 0, 256, 2, 2>, cudaFuncAttributeMaxDynamicSharedMemorySize, SM_ENC);
    cudaFuncSetAttribute(mma_gemm_kernel<0, 0, 1, 256, 1, 2>, cudaFuncAttributeMaxDynamicSharedMemorySize, SM_SEL);
    cudaFuncSetAttribute(mma_gemm_kernel<2, 1, 1, 256, 2, 2>, cudaFuncAttributeMaxDynamicSharedMemorySize, SM_B2);
    cudaFuncSetAttribute(mma_gemm_kernel<4, 0, 1, 128, 2, 2>, cudaFuncAttributeMaxDynamicSharedMemorySize, SM_OUT);

    // ---- prep (parallel, tiny) ----
    bn_partial_kernel<<<dim3(16, E), 256>>>(states, S + OFF_SUMS);
    bn_final_kernel<<<2, 256>>>(S + OFF_SUMS, S + OFF_MU, S + OFF_RSTD);
    enc_fold_kernel<<<512, 256>>>(W_enc, b_enc, S + OFF_MU, S + OFF_RSTD,
                                  Su + OFF_EHI, Su + OFF_ELO, S + OFF_BP);
    kv_pack_kernel<<<1024, 256>>>(Wk, Wv, bv, Su + OFF_KVHI, S + OFF_KVB);
    sel_pack_kernel<<<512, 256>>>(Wsel, Su + OFF_SELHI);
    mat_split_kernel<<<512, 256>>>(W_pre, Su + OFF_PREHI, Su + OFF_PRELO);
    mat_split_kernel<<<512, 256>>>(W_actor, Su + OFF_ACTHI, Su + OFF_ACTLO);
    out_pack_kernel<<<128, 256>>>(W_mean, W_logstd, b_mean, b_logstd,
                                  Su + OFF_OHI, Su + OFF_OLO, S + OFF_BOUT);

    // ---- encoder: enc fp16 planes = leaky(states @ Wenc' + bp)   A fp32, bf16 B ----
    mma_gemm_kernel<1, 2, 0, 256, 2, 2><<<dim3(2, 128, E), 256, SM_ENC>>>(
        states, nullptr, nullptr, Su + OFF_EHI, Su + OFF_ELO, S + OFF_BP,
        nullptr, Su + OFF_ENCH, Su + OFF_ENCL,
        Bb, H, Nn,
        (long long)Bb * Nn, 512LL * 32, 512LL, (long long)Bb * 256);

    // ---- fused keys|vals: KV = encs(fp16 hi) @ [Wk|Wv](fp16) — 1 MMA/k16 ----
    mma_gemm_kernel<3, 0, 1, 256, 1, 1><<<dim3(4, 128, E), 256, SM_KV>>>(
        nullptr, Su + OFF_ENCH, nullptr, Su + OFF_KVHI, nullptr, S + OFF_KVB,
        S + OFF_KV, nullptr, nullptr,
        Bb, 1024, H,
        (long long)Bb * 256, 0LL, 0LL, (long long)Bb * 1024);

    // ---- pre fp16 planes = leaky(pre_actions @ W_pre + b_pre)   bf16-3term GEMM ----
    mma_gemm_kernel<1, 2, 0, 256, 2, 2><<<dim3(2, 128, 1), 256, SM_ENC>>>(
        pre_actions, nullptr, nullptr, Su + OFF_PREHI, Su + OFF_PRELO, b_pre,
        nullptr, Su + OFF_PREH, Su + OFF_PREL,
        Bb, H, H, 0LL, 0LL, 0LL, 0LL);

    // ---- sel = pre(fp16 2-term) @ Wsel(fp16) — 2 MMAs/k16 ----
    mma_gemm_kernel<0, 0, 1, 256, 1, 2><<<dim3(2, 128, 1), 256, SM_SEL>>>(
        nullptr, Su + OFF_PREH, Su + OFF_PREL, Su + OFF_SELHI, nullptr, nullptr,
        S + OFF_SEL, nullptr, nullptr,
        Bb, AD, H, 0LL, 0LL, 0LL, 0LL);

    // ---- attention -> actor_in fp32 (d_out) + bf16 planes ----
    attn_kernel<<<Bb, 256>>>(S + OFF_KV, S + OFF_SEL, actor_in,
                             Su + OFF_AINH, Su + OFF_AINL);

    // ---- x bf16 planes = relu(actor_in @ W_actor + b_actor) ----
    mma_gemm_kernel<2, 1, 1, 256, 2, 2><<<dim3(2, 128, 1), 256, SM_B2>>>(
        nullptr, Su + OFF_AINH, Su + OFF_AINL, Su + OFF_ACTHI, Su + OFF_ACTLO, b_actor,
        nullptr, Su + OFF_XH, Su + OFF_XL,
        Bb, H, H, 0LL, 0LL, 0LL, 0LL);

    // ---- fused output GEMM: [mean | clip(logstd)] -> d_out ----
    mma_gemm_kernel<4, 0, 1, 128, 2, 2><<<dim3(1, 128, 1), 256, SM_OUT>>>(
        nullptr, Su + OFF_XH, Su + OFF_XL, Su + OFF_OHI, Su + OFF_OLO, S + OFF_BOUT,
        out, nullptr, nullptr,
        Bb, 128, H, 0LL, 0LL, 0LL, 0LL);
}